// round 17
// baseline (speedup 1.0000x reference)
#include <cuda_runtime.h>
#include <cuda_fp16.h>
#include <cstdint>

#define BB 128
#define LCDIM 256
#define LEDIM 1024
#define DDIM 256
#define MMDIM 512
#define NEGV -1e9f

// ---------------- scratch ----------------------------------------------------
__device__ __align__(16) __half g_inH[(size_t)BB * (LCDIM + LEDIM) * DDIM];  // critH | ehrH
__device__ __align__(16) __half g_ceH[(size_t)BB * (LCDIM + LEDIM) * DDIM];  // cH | eH
__device__ __align__(16) __half g_attH[(size_t)BB * (LCDIM + LEDIM) * DDIM]; // attcH | atteH
__device__ __align__(16) __half g_alignH[(size_t)BB * LCDIM * LEDIM];   // E row-major
__device__ __align__(16) __half g_alignTH[(size_t)BB * LCDIM * LEDIM];  // E^T (Le,Lc)
__device__ __align__(16) __half g_ehrTH[(size_t)BB * LEDIM * DDIM];     // masked by em
__device__ __align__(16) __half g_critTH[(size_t)BB * LCDIM * DDIM];    // masked by cm
__device__ __align__(16) __half g_WaTH[DDIM * DDIM];
__device__ __align__(16) __half g_WrTH[DDIM * 2 * DDIM];
__device__ float g_rp[(2 + 8) * BB * DDIM];
__device__ float g_colsum[BB * LEDIM];
__device__ float g_rowsum[BB * LCDIM];

// ---------------- helpers -----------------------------------------------------
__device__ __forceinline__ uint32_t smem_u32(const void* p) {
    uint32_t a;
    asm("{ .reg .u64 t; cvta.to.shared.u64 t, %1; cvt.u32.u64 %0, t; }"
        : "=r"(a) : "l"(p));
    return a;
}

#define SW128B(o) ((o) ^ (((o) >> 3) & 0x70))

__device__ __forceinline__ void ldsm4h(uint32_t& r0, uint32_t& r1, uint32_t& r2,
                                       uint32_t& r3, uint32_t addr) {
    asm volatile("ldmatrix.sync.aligned.m8n8.x4.shared.b16 {%0,%1,%2,%3}, [%4];"
                 : "=r"(r0), "=r"(r1), "=r"(r2), "=r"(r3) : "r"(addr));
}

__device__ __forceinline__ void mma16(float* c, const uint32_t* a, uint32_t b0, uint32_t b1) {
    asm volatile(
        "mma.sync.aligned.m16n8k16.row.col.f32.f16.f16.f32 "
        "{%0,%1,%2,%3}, {%4,%5,%6,%7}, {%8,%9}, {%0,%1,%2,%3};"
        : "+f"(c[0]), "+f"(c[1]), "+f"(c[2]), "+f"(c[3])
        : "r"(a[0]), "r"(a[1]), "r"(a[2]), "r"(a[3]), "r"(b0), "r"(b1));
}

#define CP16(d, g) \
    asm volatile("cp.async.cg.shared.global [%0], [%1], 16;" :: "r"(d), "l"(g))

// ---------------- FP16 tensor-core GEMM core (validated mainloop) --------------
#define BM 128
#define BN 128
#define BKH 64
#define SA_OFF(s) ((s) * 16384)
#define SB_OFF(s) (49152 + (s) * 16384)
#define GSM_TOTAL 98304
#define TP  130   // row-major epilogue tile pad (halves)
#define TPT 136   // transposed tile pad (halves): 272B rows -> 16B-aligned

__device__ __forceinline__ void gemm_core(
    const __half* __restrict__ A, const __half* __restrict__ A2, int Ksplit,
    const __half* __restrict__ B, const float* __restrict__ bias,
    void* __restrict__ Cv,
    int N, int K, long sAm, long sBn,
    int do_relu, int out_half, int sum_out,
    const float* __restrict__ rowscale,
    __half* __restrict__ expT, float* __restrict__ rowsum,
    float* __restrict__ colsum,
    const int* __restrict__ cmrow, const int* __restrict__ emcol, int expT_ld,
    int m0, int n0, char* sm)
{
    const int tid = threadIdx.x;
    const int lane = tid & 31;
    const int w = tid >> 5;
    const int wm = (w & 1) * 64;
    const int wn = (w >> 1) * 32;
    const uint32_t sb = smem_u32(sm);

    auto issueA = [&](int k0, int s) {
        const __half* Ap = A; int kb = k0;
        if (A2 && k0 >= Ksplit) { Ap = A2; kb = k0 - Ksplit; }
        uint32_t base = sb + SA_OFF(s);
#pragma unroll
        for (int i = 0; i < 4; i++) {
            int f = tid + i * 256;
            int row = f >> 3, hq = (f & 7) * 8;
            CP16(base + SW128B(row * 128 + hq * 2),
                 Ap + (long)(m0 + row) * sAm + kb + hq);
        }
    };
    auto issueB = [&](int k0, int s) {
        uint32_t base = sb + SB_OFF(s);
#pragma unroll
        for (int i = 0; i < 4; i++) {
            int f = tid + i * 256;
            int row = f >> 3, hq = (f & 7) * 8;
            CP16(base + SW128B(row * 128 + hq * 2),
                 B + (long)(n0 + row) * sBn + k0 + hq);
        }
    };

    float acc[4][4][4];
#pragma unroll
    for (int i = 0; i < 4; i++)
#pragma unroll
        for (int j = 0; j < 4; j++)
#pragma unroll
            for (int r = 0; r < 4; r++) acc[i][j][r] = 0.f;

    const int T = K / BKH;
    issueA(0, 0); issueB(0, 0);
    asm volatile("cp.async.commit_group;" ::: "memory");
    if (T > 1) {
        issueA(BKH, 1); issueB(BKH, 1);
        asm volatile("cp.async.commit_group;" ::: "memory");
    }

    for (int t = 0; t < T; t++) {
        const int s = t % 3;
        if (t == T - 1)
            asm volatile("cp.async.wait_group 0;" ::: "memory");
        else
            asm volatile("cp.async.wait_group 1;" ::: "memory");
        __syncthreads();
        if (t + 2 < T) {
            issueA((t + 2) * BKH, (t + 2) % 3);
            issueB((t + 2) * BKH, (t + 2) % 3);
            asm volatile("cp.async.commit_group;" ::: "memory");
        }

        const uint32_t abase = sb + SA_OFF(s);
        const uint32_t bbase = sb + SB_OFF(s);
#pragma unroll
        for (int ks = 0; ks < 4; ks++) {
            uint32_t a[4][4], bf[2][4];

            const int arow = lane & 15;
            const int acolh = ks * 16 + (lane >> 4) * 8;
#pragma unroll
            for (int mt = 0; mt < 4; mt++)
                ldsm4h(a[mt][0], a[mt][1], a[mt][2], a[mt][3],
                       abase + SW128B((wm + mt * 16 + arow) * 128 + acolh * 2));

            const int brow = (lane & 7) + (lane >= 16 ? 8 : 0);
            const int bcolh = ks * 16 + ((lane >> 3) & 1) * 8;
#pragma unroll
            for (int np = 0; np < 2; np++)
                ldsm4h(bf[np][0], bf[np][1], bf[np][2], bf[np][3],
                       bbase + SW128B((wn + np * 16 + brow) * 128 + bcolh * 2));

#pragma unroll
            for (int mt = 0; mt < 4; mt++)
#pragma unroll
                for (int nt = 0; nt < 4; nt++)
                    mma16(acc[mt][nt], a[mt],
                          bf[nt >> 1][(nt & 1) * 2], bf[nt >> 1][(nt & 1) * 2 + 1]);
        }
    }

    const int g = lane >> 2, tg = lane & 3;

    if (sum_out) {
        float* P = (float*)Cv + (long)(m0 / BM) * N;
#pragma unroll
        for (int nt = 0; nt < 4; nt++) {
            int col = n0 + wn + nt * 8 + tg * 2;
            float bv0 = bias ? bias[col] : 0.f;
            float bv1 = bias ? bias[col + 1] : 0.f;
            float s0 = 0.f, s1 = 0.f;
#pragma unroll
            for (int mt = 0; mt < 4; mt++)
#pragma unroll
                for (int h = 0; h < 2; h++) {
                    float v0 = acc[mt][nt][2 * h] + bv0;
                    float v1 = acc[mt][nt][2 * h + 1] + bv1;
                    if (do_relu) { v0 = fmaxf(v0, 0.f); v1 = fmaxf(v1, 0.f); }
                    s0 += v0; s1 += v1;
                }
#pragma unroll
            for (int off = 16; off >= 4; off >>= 1) {
                s0 += __shfl_xor_sync(0xffffffffu, s0, off);
                s1 += __shfl_xor_sync(0xffffffffu, s1, off);
            }
            if (g == 0) {
                atomicAdd(&P[col], s0);
                atomicAdd(&P[col + 1], s1);
            }
        }
        return;
    }

    if (expT) {
        // E = fp16(exp(acc) * 2^-4): dual-staged (row tile + transposed tile),
        // masked sums vectorized, ET write vectorized.
        __syncthreads();   // mainloop smem now free
        __half* tile  = reinterpret_cast<__half*>(sm);                    // [128][TP]
        __half* tileT = reinterpret_cast<__half*>(sm + 128 * TP * 2);     // [128][TPT]
        float* em_s = reinterpret_cast<float*>(sm + 128 * (TP + TPT) * 2);
        float* cm_s = em_s + 128;
        if (tid < 128) em_s[tid] = emcol[n0 + tid] ? 1.f : 0.f;
        else           cm_s[tid - 128] = cmrow[m0 + tid - 128] ? 1.f : 0.f;

#pragma unroll
        for (int mt = 0; mt < 4; mt++)
#pragma unroll
            for (int nt = 0; nt < 4; nt++)
#pragma unroll
                for (int h = 0; h < 2; h++) {
                    int rl = wm + mt * 16 + g + h * 8;
                    int cl = wn + nt * 8 + tg * 2;
                    float e0 = __expf(acc[mt][nt][2 * h]) * 0.0625f;
                    float e1 = __expf(acc[mt][nt][2 * h + 1]) * 0.0625f;
                    __half2 hv = __floats2half2_rn(e0, e1);
                    *reinterpret_cast<__half2*>(
                        (__half*)Cv + (long)(m0 + rl) * N + n0 + cl) = hv;
                    *reinterpret_cast<__half2*>(&tile[rl * TP + cl]) = hv;
                    tileT[cl * TPT + rl] = __low2half(hv);
                    tileT[(cl + 1) * TPT + rl] = __high2half(hv);
                }
        __syncthreads();

        if (tid < 128) {                 // rowsum (em-masked cols), vectorized
            float s = 0.f;
            const __half2* rw = reinterpret_cast<const __half2*>(&tile[tid * TP]);
#pragma unroll 8
            for (int c = 0; c < 64; c++) {
                float2 v = __half22float2(rw[c]);
                s += v.x * em_s[2 * c] + v.y * em_s[2 * c + 1];
            }
            atomicAdd(&rowsum[m0 + tid], s);
        } else {                         // colsum (cm-masked rows), vectorized
            int c = tid - 128;
            float s = 0.f;
            const __half2* rw = reinterpret_cast<const __half2*>(&tileT[c * TPT]);
#pragma unroll 8
            for (int l = 0; l < 64; l++) {
                float2 v = __half22float2(rw[l]);
                s += v.x * cm_s[2 * l] + v.y * cm_s[2 * l + 1];
            }
            atomicAdd(&colsum[n0 + c], s);
        }
        __syncthreads();

        // ET write: vectorized from tileT (16B-aligned rows)
        {
            int e_l = tid >> 1, l0h = (tid & 1) * 64;
            const uint4* src = reinterpret_cast<const uint4*>(&tileT[e_l * TPT + l0h]);
            uint4* dst = reinterpret_cast<uint4*>(
                expT + (long)(n0 + e_l) * expT_ld + m0 + l0h);
#pragma unroll
            for (int j = 0; j < 8; j++) dst[j] = src[j];
        }
        return;
    }

    float rsv[4][2];
    if (rowscale) {
#pragma unroll
        for (int mt = 0; mt < 4; mt++)
#pragma unroll
            for (int h = 0; h < 2; h++)
                rsv[mt][h] = 1.f / rowscale[m0 + wm + mt * 16 + g + h * 8];
    }

#pragma unroll
    for (int mt = 0; mt < 4; mt++) {
#pragma unroll
        for (int nt = 0; nt < 4; nt++) {
            int row = m0 + wm + mt * 16 + g;
            int col = n0 + wn + nt * 8 + tg * 2;
            float bv0 = 0.f, bv1 = 0.f;
            if (bias) { bv0 = bias[col]; bv1 = bias[col + 1]; }
#pragma unroll
            for (int h = 0; h < 2; h++) {
                long ci = (long)(row + h * 8) * N + col;
                float v0 = acc[mt][nt][2 * h] + bv0;
                float v1 = acc[mt][nt][2 * h + 1] + bv1;
                if (rowscale) { v0 *= rsv[mt][h]; v1 *= rsv[mt][h]; }
                if (do_relu) { v0 = fmaxf(v0, 0.f); v1 = fmaxf(v1, 0.f); }
                if (out_half) {
                    __half2 hv = __floats2half2_rn(v0, v1);
                    *reinterpret_cast<__half2*>((__half*)Cv + ci) = hv;
                } else {
                    *reinterpret_cast<float2*>((float*)Cv + ci) = make_float2(v0, v1);
                }
            }
        }
    }
}

// ---------------- plain wrapper (ce-GEMM, r-GEMM) ------------------------------
__global__ __launch_bounds__(256, 2) void gemm_h(
    const __half* __restrict__ A, const __half* __restrict__ A2, int Ksplit,
    const __half* __restrict__ B, const float* __restrict__ bias,
    void* __restrict__ Cv, int N, int K, long sAm, long sBn,
    int do_relu, int out_half, int sum_out)
{
    extern __shared__ char sm[];
    gemm_core(A, A2, Ksplit, B, bias, Cv, N, K, sAm, sBn,
              do_relu, out_half, sum_out, nullptr,
              nullptr, nullptr, nullptr, nullptr, nullptr, 0,
              blockIdx.y * BM, blockIdx.x * BN, sm);
}

// ---------------- align wrapper: E + E^T + masked row/col sums -----------------
__global__ __launch_bounds__(256, 2) void gemm_align(
    const __half* __restrict__ cH, const __half* __restrict__ eH,
    __half* __restrict__ E, __half* __restrict__ ET,
    float* __restrict__ rowsum, float* __restrict__ colsum,
    const int* __restrict__ cmask, const int* __restrict__ emask)
{
    extern __shared__ char sm[];
    const long LCD = (long)LCDIM * DDIM;
    const long LED = (long)LEDIM * DDIM;
    const long LCE = (long)LCDIM * LEDIM;
    long z = blockIdx.z;
    gemm_core(cH + z * LCD, nullptr, 0, eH + z * LED, nullptr,
              E + z * LCE, LEDIM, DDIM, DDIM, DDIM,
              0, 1, 0, nullptr,
              ET + z * LCE, rowsum + z * LCDIM, colsum + z * LEDIM,
              cmask + z * LCDIM, emask + z * LEDIM, LCDIM,
              blockIdx.y * BM, blockIdx.x * BN, sm);
}

// ---------------- merged att wrapper (1-D grid, long-K tiles first) ------------
__global__ __launch_bounds__(256, 2) void gemm_att(
    const __half* __restrict__ E, const __half* __restrict__ ehrTH,
    __half* __restrict__ attcH,
    const __half* __restrict__ ET, const __half* __restrict__ critTH,
    __half* __restrict__ atteH,
    const float* __restrict__ rowsum, const float* __restrict__ colsum)
{
    extern __shared__ char sm[];
    const long LCD = (long)LCDIM * DDIM;
    const long LED = (long)LEDIM * DDIM;
    const long LCE = (long)LCDIM * LEDIM;
    int idx = blockIdx.x;
    if (idx < 512) {
        int z = idx >> 2, r = idx & 3;
        gemm_core(E + (long)z * LCE, nullptr, 0, ehrTH + (long)z * LED, nullptr,
                  attcH + (long)z * LCD, DDIM, LEDIM, LEDIM, LEDIM,
                  0, 1, 0, rowsum + (long)z * LCDIM,
                  nullptr, nullptr, nullptr, nullptr, nullptr, 0,
                  (r >> 1) * BM, (r & 1) * BN, sm);
    } else {
        int i2 = idx - 512;
        int z = i2 >> 4, r = i2 & 15;
        gemm_core(ET + (long)z * LCE, nullptr, 0, critTH + (long)z * LCD, nullptr,
                  atteH + (long)z * LED, DDIM, LCDIM, LCDIM, LCDIM,
                  0, 1, 0, colsum + (long)z * LEDIM,
                  nullptr, nullptr, nullptr, nullptr, nullptr, 0,
                  (r >> 1) * BM, (r & 1) * BN, sm);
    }
}

// ---------------- prep3: fat 32x256 row-slab prologue --------------------------
// grid (1, 72, BB): ty<8 crit slab, 8<=ty<40 ehr slab; z==0 && ty>=40:
//   tw=ty-40: tw<8 Wa slab, tw<24 Wr slab, 24<=tw<32 zero slices.
// Per slab: fp32 load (float4), fp16 row-major write (uint4), fp16 masked
// transposed write (uint4, conflict-free via 257-word pad).
__global__ __launch_bounds__(256) void prep3_k(
    const float* __restrict__ crit, __half* __restrict__ critH,
    __half* __restrict__ critTH,
    const float* __restrict__ ehr, __half* __restrict__ ehrH,
    __half* __restrict__ ehrTH,
    const int* __restrict__ cmask, const int* __restrict__ emask,
    const float* __restrict__ Wa, __half* __restrict__ WaT,
    const float* __restrict__ Wr, __half* __restrict__ WrT,
    float* __restrict__ z1, int n1, float* __restrict__ z2, int n2,
    float* __restrict__ z3, int n3)
{
    __shared__ float tile[32][257];
    __shared__ float msk[32];
    const long LCD = (long)LCDIM * DDIM, LED = (long)LEDIM * DDIM;
    const int tid = threadIdx.x;
    int b = blockIdx.z, ty = blockIdx.y;

    const float* in; __half* outR; __half* outT; const int* mask;
    int R, r0;
    if (ty < 8) {
        in = crit + b * LCD; outR = critH + b * LCD; outT = critTH + b * LCD;
        mask = cmask + b * LCDIM; R = LCDIM; r0 = ty * 32;
    } else if (ty < 40) {
        in = ehr + b * LED; outR = ehrH + b * LED; outT = ehrTH + b * LED;
        mask = emask + b * LEDIM; R = LEDIM; r0 = (ty - 8) * 32;
    } else {
        if (b != 0) return;
        int tw = ty - 40;
        if (tw >= 24) {                     // 8 zero slices
            int s = tw - 24;
            for (int j = s * 256 + tid; j < n1; j += 2048) z1[j] = 0.f;
            for (int j = s * 256 + tid; j < n2; j += 2048) z2[j] = 0.f;
            for (int j = s * 256 + tid; j < n3; j += 2048) z3[j] = 0.f;
            return;
        }
        if (tw < 8) { in = Wa; outR = nullptr; outT = WaT; R = DDIM; r0 = tw * 32; }
        else        { in = Wr; outR = nullptr; outT = WrT; R = 2 * DDIM; r0 = (tw - 8) * 32; }
        mask = nullptr;
        in += (long)r0 * DDIM;
    }
    if (mask) in += 0;  // data slabs already batch-offset; add row offset below

    const float* src = (ty < 40) ? in + (long)r0 * DDIM : in;

    // load 32x256 fp32 (2048 float4; 8 per thread)
#pragma unroll
    for (int i = 0; i < 8; i++) {
        int f = tid + i * 256;
        int row = f >> 6, c4 = (f & 63) * 4;
        float4 v = *reinterpret_cast<const float4*>(src + (long)row * DDIM + c4);
        tile[row][c4] = v.x; tile[row][c4 + 1] = v.y;
        tile[row][c4 + 2] = v.z; tile[row][c4 + 3] = v.w;
    }
    if (tid < 32) msk[tid] = mask ? (mask[r0 + tid] ? 1.f : 0.f) : 1.f;
    __syncthreads();

    // row-major fp16 write (only data slabs): 1024 uint4, 4 per thread
    if (outR) {
        __half* oR = outR + (long)r0 * DDIM;
#pragma unroll
        for (int i = 0; i < 4; i++) {
            int f = tid + i * 256;
            int row = f >> 5, h8 = (f & 31) * 8;
            __half2 p[4];
#pragma unroll
            for (int q = 0; q < 4; q++)
                p[q] = __floats2half2_rn(tile[row][h8 + 2 * q], tile[row][h8 + 2 * q + 1]);
            *reinterpret_cast<uint4*>(oR + (long)row * DDIM + h8) =
                *reinterpret_cast<uint4*>(p);
        }
    }

    // transposed masked fp16 write: thread = column c, 32 rows -> 4 uint4
    {
        int c = tid;
        __half2 p[16];
#pragma unroll
        for (int q = 0; q < 16; q++)
            p[q] = __floats2half2_rn(tile[2 * q][c] * msk[2 * q],
                                     tile[2 * q + 1][c] * msk[2 * q + 1]);
        uint4* dst = reinterpret_cast<uint4*>(outT + (long)c * R + r0);
        const uint4* srcp = reinterpret_cast<const uint4*>(p);
#pragma unroll
        for (int j = 0; j < 4; j++) dst[j] = srcp[j];
    }
}

// ---------------- final MLP ----------------------------------------------------
__global__ __launch_bounds__(512) void final_kernel(
    const float* __restrict__ r1p, const float* __restrict__ r2p,
    const float* __restrict__ Wm, const float* __restrict__ bm,
    const float* __restrict__ Wo, const float* __restrict__ bo,
    float* __restrict__ out)
{
    int b = blockIdx.x;
    int t = threadIdx.x;

    __shared__ float ms[4 * DDIM];
    __shared__ float hs[MMDIM];

    if (t < DDIM) {
        float r1 = 0.f, r2 = 0.f;
#pragma unroll
        for (int s = 0; s < 2; s++) r1 += r1p[(b * 2 + s) * DDIM + t];
#pragma unroll
        for (int s = 0; s < 8; s++) r2 += r2p[(b * 8 + s) * DDIM + t];
        ms[t] = r1;
        ms[DDIM + t] = r2;
        ms[2 * DDIM + t] = r1 * r2;
        ms[3 * DDIM + t] = r1 - r2;
    }
    __syncthreads();

    float acc = bm[t];
#pragma unroll 8
    for (int k = 0; k < 4 * DDIM; k++) acc += ms[k] * Wm[(long)k * MMDIM + t];
    hs[t] = fmaxf(acc, 0.f);
    __syncthreads();

    int w = t >> 5, lane = t & 31;
    if (w < 3) {
        float s = 0.f;
        for (int j = lane; j < MMDIM; j += 32) s += hs[j] * Wo[j * 3 + w];
#pragma unroll
        for (int off = 16; off; off >>= 1) s += __shfl_down_sync(0xffffffffu, s, off);
        if (lane == 0) out[b * 3 + w] = s + bo[w];
    }
}

// ---------------- launch -------------------------------------------------------
extern "C" void kernel_launch(void* const* d_in, const int* in_sizes, int n_in,
                              void* d_out, int out_size)
{
    const float *criteria, *ehr, *Wa, *ba, *Wr, *br, *Wm, *bm, *Wo, *bo;
    const int *cmask, *emask;

    if (in_sizes[2] == BB * LCDIM) {
        criteria = (const float*)d_in[0]; ehr = (const float*)d_in[1];
        cmask = (const int*)d_in[2]; emask = (const int*)d_in[3];
        Wa = (const float*)d_in[4]; ba = (const float*)d_in[5];
        Wr = (const float*)d_in[6]; br = (const float*)d_in[7];
        Wm = (const float*)d_in[8]; bm = (const float*)d_in[9];
        Wo = (const float*)d_in[10]; bo = (const float*)d_in[11];
    } else {
        criteria = (const float*)d_in[0]; ehr = (const float*)d_in[1];
        Wa = (const float*)d_in[2]; ba = (const float*)d_in[3];
        Wr = (const float*)d_in[4]; br = (const float*)d_in[5];
        Wm = (const float*)d_in[6]; bm = (const float*)d_in[7];
        Wo = (const float*)d_in[8]; bo = (const float*)d_in[9];
        cmask = (const int*)d_in[10]; emask = (const int*)d_in[11];
    }

    __half *inH, *ceH, *attH, *alignH, *alignTH, *ehrTH, *critTH, *WaTH, *WrTH;
    float *rp, *colsum, *rowsum;
    cudaGetSymbolAddress((void**)&inH,     g_inH);
    cudaGetSymbolAddress((void**)&ceH,     g_ceH);
    cudaGetSymbolAddress((void**)&attH,    g_attH);
    cudaGetSymbolAddress((void**)&alignH,  g_alignH);
    cudaGetSymbolAddress((void**)&alignTH, g_alignTH);
    cudaGetSymbolAddress((void**)&ehrTH,   g_ehrTH);
    cudaGetSymbolAddress((void**)&critTH,  g_critTH);
    cudaGetSymbolAddress((void**)&WaTH,    g_WaTH);
    cudaGetSymbolAddress((void**)&WrTH,    g_WrTH);
    cudaGetSymbolAddress((void**)&rp,      g_rp);
    cudaGetSymbolAddress((void**)&colsum,  g_colsum);
    cudaGetSymbolAddress((void**)&rowsum,  g_rowsum);

    const long LCD = (long)LCDIM * DDIM;   // 65536

    __half* critH = inH;
    __half* ehrH  = inH + (size_t)BB * LCD;
    __half* cH    = ceH;
    __half* eH    = ceH + (size_t)BB * LCD;
    float*  r1p   = rp;
    float*  r2p   = rp + (size_t)BB * 2 * DDIM;

    cudaFuncSetAttribute(gemm_h, cudaFuncAttributeMaxDynamicSharedMemorySize,
                         GSM_TOTAL);
    cudaFuncSetAttribute(gemm_align, cudaFuncAttributeMaxDynamicSharedMemorySize,
                         GSM_TOTAL);
    cudaFuncSetAttribute(gemm_att, cudaFuncAttributeMaxDynamicSharedMemorySize,
                         GSM_TOTAL);

    const int MTOT = BB * (LCDIM + LEDIM);          // 163840 rows, 1280 tiles

    // prologue: fat-slab prep (incl. weights + zeroing)
    prep3_k<<<dim3(1, 72, BB), 256>>>(criteria, critH, critTH, ehr, ehrH, ehrTH,
                                      cmask, emask, Wa, WaTH, Wr, WrTH,
                                      rp, (2 + 8) * BB * DDIM,
                                      colsum, BB * LEDIM, rowsum, BB * LCDIM);

    // [c ; e] = relu([criteria; ehr] @ Wa + ba) -> fp16
    gemm_h<<<dim3(DDIM / BN, MTOT / BM, 1), 256, GSM_TOTAL>>>(
        inH, nullptr, 0, WaTH, ba, ceH, DDIM, DDIM, DDIM, DDIM, 1, 1, 0);

    // E = fp16(exp(c@e^T) * 2^-4) + E^T + masked row/col sums (fused)
    gemm_align<<<dim3(LEDIM / BN, LCDIM / BM, BB), 256, GSM_TOTAL>>>(
        cH, eH, alignH, alignTH, rowsum, colsum, cmask, emask);

    // att_c + att_e with 1/rowsum, 1/colsum scaling (one launch)
    gemm_att<<<2560, 256, GSM_TOTAL>>>(alignH, ehrTH, attH,
                                       alignTH, critTH, attH + (size_t)BB * LCD,
                                       rowsum, colsum);

    // [r1p ; r2p] = rowsum(relu([att ; in] @ Wr + br))
    gemm_h<<<dim3(DDIM / BN, MTOT / BM, 1), 256, GSM_TOTAL>>>(
        attH, inH, DDIM, WrTH, br, rp, DDIM, 2 * DDIM, DDIM, 2 * DDIM, 1, 0, 1);

    final_kernel<<<BB, 512>>>(r1p, r2p, Wm, bm, Wo, bo, (float*)d_out);
}